// round 14
// baseline (speedup 1.0000x reference)
#include <cuda_runtime.h>
#include <cuda_bf16.h>
#include <math.h>

// Problem constants (shapes fixed by the dataset)
#define NN 50000
#define NE 800000
#define D0 64   // x features
#define D1 96   // hidden
#define D2 64   // out

#define GRID 740    // 5 blocks/SM * 148 SMs — fully balanced persistent grid
#define NT   256    // threads per block

// ---------------- scratch (device globals: no allocation allowed) ----------
__device__ int      g_is64;
__device__ int      g_csr[NE];
__device__ int      g_cnt[NN];
__device__ int      g_row[NN + 1];
__device__ int      g_cur[NN];
__device__ float    g_dis[NN];
__device__ int      g_bsum[GRID];
__device__ int      g_bpre[GRID];
__device__ unsigned g_barrier_ctr;   // monotonic across launches (replay-safe)
__device__ unsigned g_steal[4];      // work-steal: gemm1,agg1,gemm2,agg2
__device__ float    g_h1 [NN * D1];  // x@W1 (UNSCALED)
__device__ float    g_h  [NN * D1];  // relu(layer1)
__device__ float    g_hs2[NN * D2];  // (h@W2)*dis[row]

__device__ __forceinline__ float act_relu(float v)    { return fmaxf(v, 0.0f); }
__device__ __forceinline__ float act_sigmoid(float v) { return 1.0f / (1.0f + expf(-v)); }

// ---------------- software grid barrier ------------------------------------
__device__ __forceinline__ void gbar() {
    __threadfence();
    __syncthreads();
    if (threadIdx.x == 0) {
        unsigned old = atomicAdd(&g_barrier_ctr, 1u);
        unsigned target = (old / GRID) * GRID + GRID;
        while ((int)(*(volatile unsigned*)&g_barrier_ctr - target) < 0)
            __nanosleep(64);
        __threadfence();
    }
    __syncthreads();
}

// ---------------- bf16 split helpers ---------------------------------------
// Pack (x,y) -> bf16x2 hi and lo (residual) words.
__device__ __forceinline__ void split2(float x, float y, unsigned& hi, unsigned& lo) {
    __nv_bfloat16 hx = __float2bfloat16(x), hy = __float2bfloat16(y);
    __nv_bfloat16 lx = __float2bfloat16(x - __bfloat162float(hx));
    __nv_bfloat16 ly = __float2bfloat16(y - __bfloat162float(hy));
    hi = ((unsigned)__bfloat16_as_ushort(hy) << 16) | (unsigned)__bfloat16_as_ushort(hx);
    lo = ((unsigned)__bfloat16_as_ushort(ly) << 16) | (unsigned)__bfloat16_as_ushort(lx);
}

// classic tensor-core mma (sm_80+, no arch-feature suffix needed)
__device__ __forceinline__ void mma16816(float* c, unsigned a0, unsigned a1,
                                         unsigned a2, unsigned a3,
                                         unsigned b0, unsigned b1) {
    asm volatile(
        "mma.sync.aligned.m16n8k16.row.col.f32.bf16.bf16.f32 "
        "{%0,%1,%2,%3}, {%4,%5,%6,%7}, {%8,%9}, {%0,%1,%2,%3};"
        : "+f"(c[0]), "+f"(c[1]), "+f"(c[2]), "+f"(c[3])
        : "r"(a0), "r"(a1), "r"(a2), "r"(a3), "r"(b0), "r"(b1));
}

// ---------------- tensor-core GEMM phase (work-stealing 32-row tiles) -------
// HS[row][c] = (SCALE ? dis[row] : 1) * sum_k X[row][k]*W[k][c], fp32 in/out.
// 3-term bf16 split: D = Ah*Bh + Ah*Bl + Al*Bh (fp32 accumulate).
// Smem rows use pitch == 16 (mod 128) bytes -> all fragment LDS.32 patterns
// are bank-conflict-free. W^T staged once per phase; X tile per steal.
template <int IN, int OUT, bool SCALE>
__device__ void gemm_mma(const float* __restrict__ X, const float* __restrict__ Wm,
                         float* __restrict__ HS, char* buf,
                         unsigned* ctr, volatile int* sStealP) {
    constexpr int PITCH  = (IN == 64) ? 144 : 208;  // bytes/row, ==16 mod 128
    constexpr int WB     = OUT * PITCH;
    constexpr int XB     = 32 * PITCH;
    constexpr int KSTEPS = IN / 16;
    constexpr int NTILES = OUT / 32;    // n-tiles per warp (3 or 2)
    constexpr int KP     = IN / 2;      // bf16 pairs per row

    char* sWh = buf;
    char* sWl = buf + WB;
    char* sXh = buf + 2 * WB;
    char* sXl = buf + 2 * WB + XB;

    int t = threadIdx.x, w = t >> 5, lane = t & 31;
    int q = lane >> 2, c = lane & 3;

    // ---- stage W^T (hi/lo) once per phase: sW[n][k] pairs along k
    for (int i = t; i < OUT * KP; i += NT) {
        int n = i / KP, kp = i % KP;
        float w0 = Wm[(2 * kp) * OUT + n];
        float w1 = Wm[(2 * kp + 1) * OUT + n];
        unsigned hi, lo;
        split2(w0, w1, hi, lo);
        *(unsigned*)(sWh + n * PITCH + kp * 4) = hi;
        *(unsigned*)(sWl + n * PITCH + kp * 4) = lo;
    }

    int r0    = (w & 1) * 16;           // row-group within tile
    int npart = (w >> 1) * (OUT / 4);   // column part base
    const int ntile = (NN + 31) / 32;

    for (;;) {
        __syncthreads();   // W staged / prior iter readers done with sX+sSteal
        if (t == 0) *sStealP = (int)atomicAdd(ctr, 1u);
        __syncthreads();
        int tile = *sStealP;
        if (tile >= ntile) break;
        int row0 = tile * 32;

        // ---- stage X tile (hi/lo), pairs along k
        for (int i = t; i < 32 * KP; i += NT) {
            int r = i / KP, kp = i % KP;
            int gr = row0 + r;
            float2 v = make_float2(0.f, 0.f);
            if (gr < NN) v = *(const float2*)&X[gr * IN + 2 * kp];
            unsigned hi, lo;
            split2(v.x, v.y, hi, lo);
            *(unsigned*)(sXh + r * PITCH + kp * 4) = hi;
            *(unsigned*)(sXl + r * PITCH + kp * 4) = lo;
        }
        __syncthreads();

        float C[NTILES][4];
#pragma unroll
        for (int nt = 0; nt < NTILES; nt++)
#pragma unroll
            for (int j = 0; j < 4; j++) C[nt][j] = 0.0f;

        const char* aH = sXh + (r0 + q) * PITCH + c * 4;
        const char* aL = sXl + (r0 + q) * PITCH + c * 4;

#pragma unroll
        for (int s = 0; s < KSTEPS; s++) {
            int ko = 32 * s;
            unsigned ah0 = *(const unsigned*)(aH + ko);
            unsigned ah1 = *(const unsigned*)(aH + ko + 8 * PITCH);
            unsigned ah2 = *(const unsigned*)(aH + ko + 16);
            unsigned ah3 = *(const unsigned*)(aH + ko + 8 * PITCH + 16);
            unsigned al0 = *(const unsigned*)(aL + ko);
            unsigned al1 = *(const unsigned*)(aL + ko + 8 * PITCH);
            unsigned al2 = *(const unsigned*)(aL + ko + 16);
            unsigned al3 = *(const unsigned*)(aL + ko + 8 * PITCH + 16);
#pragma unroll
            for (int nt = 0; nt < NTILES; nt++) {
                int n0 = npart + nt * 8;
                const char* bB = sWh + (n0 + q) * PITCH + c * 4 + ko;
                unsigned bh0 = *(const unsigned*)bB;
                unsigned bh1 = *(const unsigned*)(bB + 16);
                const char* bL = sWl + (n0 + q) * PITCH + c * 4 + ko;
                unsigned bl0 = *(const unsigned*)bL;
                unsigned bl1 = *(const unsigned*)(bL + 16);
                mma16816(C[nt], ah0, ah1, ah2, ah3, bh0, bh1);
                mma16816(C[nt], ah0, ah1, ah2, ah3, bl0, bl1);
                mma16816(C[nt], al0, al1, al2, al3, bh0, bh1);
            }
        }

        // ---- epilogue: c0/c1 = cols 2c,2c+1 of row q; c2/c3 = row q+8
        int gr0 = row0 + r0 + q;
        int gr1 = gr0 + 8;
        float d0 = (SCALE && gr0 < NN) ? g_dis[gr0] : 1.0f;
        float d1 = (SCALE && gr1 < NN) ? g_dis[gr1] : 1.0f;
#pragma unroll
        for (int nt = 0; nt < NTILES; nt++) {
            int n0 = npart + nt * 8 + 2 * c;
            if (gr0 < NN)
                *(float2*)&HS[gr0 * OUT + n0] = make_float2(C[nt][0] * d0, C[nt][1] * d0);
            if (gr1 < NN)
                *(float2*)&HS[gr1 * OUT + n0] = make_float2(C[nt][2] * d1, C[nt][3] * d1);
        }
    }
}

// ---------------- per-node aggregation bodies (R12-proven) ------------------
__device__ __forceinline__ void agg1_node(int node, const float4* __restrict__ H4,
                                          const float* __restrict__ b,
                                          float* __restrict__ OUT,
                                          int lane, bool on) {
    constexpr int C4 = D1 / 4;   // 24
    int beg = g_row[node], end = g_row[node + 1];
    float di = g_dis[node];
    float4 acc = make_float4(0.f, 0.f, 0.f, 0.f);
    if (on) {
        float4 hv = H4[node * C4 + lane];
        acc.x = hv.x * di; acc.y = hv.y * di;
        acc.z = hv.z * di; acc.w = hv.w * di;
    }
    int j = beg;
    for (; j + 4 <= end; j += 4) {
        int s0 = g_csr[j + 0], s1 = g_csr[j + 1];
        int s2 = g_csr[j + 2], s3 = g_csr[j + 3];
        float d0 = g_dis[s0], d1 = g_dis[s1], d2 = g_dis[s2], d3 = g_dis[s3];
        if (on) {
            float4 v0 = H4[s0 * C4 + lane];
            float4 v1 = H4[s1 * C4 + lane];
            float4 v2 = H4[s2 * C4 + lane];
            float4 v3 = H4[s3 * C4 + lane];
            acc.x = fmaf(v0.x, d0, fmaf(v1.x, d1, fmaf(v2.x, d2, fmaf(v3.x, d3, acc.x))));
            acc.y = fmaf(v0.y, d0, fmaf(v1.y, d1, fmaf(v2.y, d2, fmaf(v3.y, d3, acc.y))));
            acc.z = fmaf(v0.z, d0, fmaf(v1.z, d1, fmaf(v2.z, d2, fmaf(v3.z, d3, acc.z))));
            acc.w = fmaf(v0.w, d0, fmaf(v1.w, d1, fmaf(v2.w, d2, fmaf(v3.w, d3, acc.w))));
        }
    }
    for (; j < end; j++) {
        int s0 = g_csr[j];
        float d0 = g_dis[s0];
        if (on) {
            float4 v = H4[s0 * C4 + lane];
            acc.x = fmaf(v.x, d0, acc.x); acc.y = fmaf(v.y, d0, acc.y);
            acc.z = fmaf(v.z, d0, acc.z); acc.w = fmaf(v.w, d0, acc.w);
        }
    }
    if (on) {
        float4 bb = ((const float4*)b)[lane];
        float4 o;
        o.x = act_relu(fmaf(di, acc.x, bb.x));
        o.y = act_relu(fmaf(di, acc.y, bb.y));
        o.z = act_relu(fmaf(di, acc.z, bb.z));
        o.w = act_relu(fmaf(di, acc.w, bb.w));
        ((float4*)OUT)[node * C4 + lane] = o;
    }
}

__device__ __forceinline__ void agg2_node(int node, const float2* __restrict__ H2,
                                          const float* __restrict__ b,
                                          float* __restrict__ OUT, int lane) {
    constexpr int C2 = D2 / 2;   // 32
    int beg = g_row[node], end = g_row[node + 1];
    float2 acc = H2[node * C2 + lane];
    int j = beg;
    for (; j + 4 <= end; j += 4) {
        int s0 = g_csr[j + 0], s1 = g_csr[j + 1];
        int s2 = g_csr[j + 2], s3 = g_csr[j + 3];
        float2 v0 = H2[s0 * C2 + lane];
        float2 v1 = H2[s1 * C2 + lane];
        float2 v2 = H2[s2 * C2 + lane];
        float2 v3 = H2[s3 * C2 + lane];
        acc.x += (v0.x + v1.x) + (v2.x + v3.x);
        acc.y += (v0.y + v1.y) + (v2.y + v3.y);
    }
    for (; j < end; j++) {
        int s0 = g_csr[j];
        float2 v = H2[s0 * C2 + lane];
        acc.x += v.x; acc.y += v.y;
    }
    float d = g_dis[node];
    float2 bb = ((const float2*)b)[lane];
    float2 o;
    o.x = act_sigmoid(fmaf(d, acc.x, bb.x));
    o.y = act_sigmoid(fmaf(d, acc.y, bb.y));
    ((float2*)OUT)[node * C2 + lane] = o;
}

// ---------------- the single fused persistent kernel -----------------------
// smem: gemm buffer 39,936B (layer2 worst case) + scan 1KB -> ~41KB static;
// 5 blocks/SM (<=51 regs).
__global__ void __launch_bounds__(NT, 5)
k_fused(const float* __restrict__ x, const void* __restrict__ ep,
        const float* __restrict__ W1, const float* __restrict__ b1,
        const float* __restrict__ W2, const float* __restrict__ b2,
        float* __restrict__ out) {
    __shared__ __align__(16) char sBuf[39936];
    __shared__ int sScan[NT];
    __shared__ int s_nz;
    __shared__ int sSteal;

    int t   = threadIdx.x;
    int blk = blockIdx.x;
    int gid = blk * NT + t;
    int w   = t >> 5, lane = t & 31;

    // ---- P0: zero histogram; block 0 detects edge dtype; reset steal[3].
    // Values in [0,50000): little-endian int64 => odd 32-bit words of the
    // first 1024 entries are all 0; int32 => they are random edge ids.
    if (gid == 0) g_steal[3] = 0;
    if (gid < NN) g_cnt[gid] = 0;
    if (blk == 0) {
        const int* e = (const int*)ep;
        int local = 0;
#pragma unroll
        for (int q = 0; q < 4; q++) local |= e[2 * (t * 4 + q) + 1];
        if (t == 0) s_nz = 0;
        __syncthreads();
        if (local) atomicOr(&s_nz, 1);
        __syncthreads();
        if (t == 0) g_is64 = (s_nz == 0) ? 1 : 0;
    }
    gbar();
    int is64 = __ldcg(&g_is64);

    // ---- P1: in-degree histogram, then steal gemm1 tiles (tensor cores).
    if (is64) {
        const longlong2* p = (const longlong2*)ep;
        for (int i = gid; i < NE / 2; i += GRID * NT) {
            longlong2 dd = p[NE / 2 + i];
            atomicAdd(&g_cnt[(int)dd.x], 1);
            atomicAdd(&g_cnt[(int)dd.y], 1);
        }
    } else {
        const int2* p = (const int2*)ep;
        for (int i = gid; i < NE / 2; i += GRID * NT) {
            int2 dd = p[NE / 2 + i];
            atomicAdd(&g_cnt[dd.x], 1);
            atomicAdd(&g_cnt[dd.y], 1);
        }
    }
    gemm_mma<D0, D1, false>(x, W1, g_h1, sBuf, &g_steal[0], &sSteal);
    gbar();

    // ---- P2a: block-local inclusive scan of counts
    int c = (gid < NN) ? __ldcg(&g_cnt[gid]) : 0;
    sScan[t] = c;
    __syncthreads();
#pragma unroll
    for (int off = 1; off < NT; off <<= 1) {
        int v = sScan[t];
        int a = (t >= off) ? sScan[t - off] : 0;
        __syncthreads();
        sScan[t] = v + a;
        __syncthreads();
    }
    int incl = sScan[t];
    if (t == NT - 1) g_bsum[blk] = incl;
    gbar();

    // ---- P2b: block 0 scans the GRID block totals
    if (blk == 0) {
        constexpr int PB = (GRID + NT - 1) / NT;   // 3
        int loc[PB];
        int s = 0;
#pragma unroll
        for (int q = 0; q < PB; q++) {
            int idx = t * PB + q;
            loc[q] = (idx < GRID) ? __ldcg(&g_bsum[idx]) : 0;
            s += loc[q];
        }
        sScan[t] = s;
        __syncthreads();
#pragma unroll
        for (int off = 1; off < NT; off <<= 1) {
            int v = sScan[t];
            int ad = (t >= off) ? sScan[t - off] : 0;
            __syncthreads();
            sScan[t] = v + ad;
            __syncthreads();
        }
        int run = sScan[t] - s;
#pragma unroll
        for (int q = 0; q < PB; q++) {
            int idx = t * PB + q;
            if (idx < GRID) { g_bpre[idx] = run; run += loc[q]; }
        }
    }
    gbar();

    // ---- P2c: write row/cur/dis; reset steal[0]
    if (gid < NN) {
        int base = __ldcg(&g_bpre[blk]);
        int excl = base + incl - c;
        g_row[gid] = excl;
        g_cur[gid] = excl;
        g_dis[gid] = rsqrtf((float)c + 1.0f);
    }
    if (gid == 0) { g_row[NN] = NE; g_steal[0] = 0; }
    gbar();

    // ---- P3: CSR scatter
    if (is64) {
        const long long* p = (const long long*)ep;
        for (int e = gid; e < NE; e += GRID * NT) {
            int s = (int)p[e];
            int d = (int)p[NE + e];
            int pos = atomicAdd(&g_cur[d], 1);
            g_csr[pos] = s;
        }
    } else {
        const int* p = (const int*)ep;
        for (int e = gid; e < NE; e += GRID * NT) {
            int s = p[e];
            int d = p[NE + e];
            int pos = atomicAdd(&g_cur[d], 1);
            g_csr[pos] = s;
        }
    }
    gbar();

    // ---- P4: layer-1 aggregation (stolen chunks of 16 nodes, 2/warp)
    {
        const float4* H4 = (const float4*)g_h1;
        bool on = lane < (D1 / 4);
        for (;;) {
            __syncthreads();
            if (t == 0) sSteal = (int)atomicAdd(&g_steal[1], 1u);
            __syncthreads();
            int base = sSteal * 16;
            if (base >= NN) break;
#pragma unroll
            for (int q = 0; q < 2; q++) {
                int node = base + w * 2 + q;
                if (node < NN) agg1_node(node, H4, b1, g_h, lane, on);
            }
        }
    }
    gbar();

    // ---- P5: layer-2 GEMM (tensor cores, scaled epilogue)
    gemm_mma<D1, D2, true>(g_h, W2, g_hs2, sBuf, &g_steal[2], &sSteal);
    gbar();

    // ---- P6: layer-2 aggregation; reset steal[1],[2]
    if (gid == 0) { g_steal[1] = 0; g_steal[2] = 0; }
    {
        const float2* H2 = (const float2*)g_hs2;
        for (;;) {
            __syncthreads();
            if (t == 0) sSteal = (int)atomicAdd(&g_steal[3], 1u);
            __syncthreads();
            int base = sSteal * 16;
            if (base >= NN) break;
#pragma unroll
            for (int q = 0; q < 2; q++) {
                int node = base + w * 2 + q;
                if (node < NN) agg2_node(node, H2, b2, out, lane);
            }
        }
    }
}

// ---------------- launch: ONE kernel ---------------------------------------
extern "C" void kernel_launch(void* const* d_in, const int* in_sizes, int n_in,
                              void* d_out, int out_size) {
    const float* x  = (const float*)d_in[0];
    const void*  ei = d_in[1];
    const float* W1 = (const float*)d_in[2];
    const float* b1 = (const float*)d_in[3];
    const float* W2 = (const float*)d_in[4];
    const float* b2 = (const float*)d_in[5];
    float* out = (float*)d_out;

    k_fused<<<GRID, NT>>>(x, ei, W1, b1, W2, b2, out);
}

// round 15
// speedup vs baseline: 1.1167x; 1.1167x over previous
#include <cuda_runtime.h>
#include <math.h>

// Problem constants (shapes fixed by the dataset)
#define NN 50000
#define NE 800000
#define D0 64   // x features
#define D1 96   // hidden
#define D2 64   // out

#define GRID 444    // 3 blocks/SM * 148 SMs (63KB smem/block)
#define NT   256    // threads per block

// ---------------- scratch (device globals: no allocation allowed) ----------
__device__ int      g_is64;
__device__ int      g_csr[NE];
__device__ int      g_cnt[NN];
__device__ int      g_row[NN + 1];
__device__ int      g_cur[NN];
__device__ float    g_dis[NN];
__device__ int      g_bsum[GRID];
__device__ int      g_bpre[GRID];
__device__ unsigned g_barrier_ctr;   // monotonic across launches (replay-safe)
__device__ unsigned g_steal[3];      // work-steal: aggx, fused-gemm, agg2
__device__ float    g_z  [NN * D0];  // D-hat(x)  (fully normalized agg of x)
__device__ float    g_hs2[NN * D2];  // (relu(zW1+b1) W2) * dis[row]

__device__ __forceinline__ float act_relu(float v)    { return fmaxf(v, 0.0f); }
__device__ __forceinline__ float act_sigmoid(float v) { return 1.0f / (1.0f + expf(-v)); }

// ---------------- software grid barrier ------------------------------------
__device__ __forceinline__ void gbar() {
    __threadfence();
    __syncthreads();
    if (threadIdx.x == 0) {
        unsigned old = atomicAdd(&g_barrier_ctr, 1u);
        unsigned target = (old / GRID) * GRID + GRID;
        while ((int)(*(volatile unsigned*)&g_barrier_ctr - target) < 0)
            __nanosleep(64);
        __threadfence();
    }
    __syncthreads();
}

// ---------------- per-node aggregation bodies -------------------------------
// Layer-1 agg on RAW x (64f): z_i = dis_i * ( dis_i*x_i + sum_e dis_src*x_src )
__device__ __forceinline__ void aggx_node(int node, const float2* __restrict__ X2,
                                          float* __restrict__ Z, int lane) {
    constexpr int C2 = D0 / 2;   // 32, all lanes active
    int beg = g_row[node], end = g_row[node + 1];
    float di = g_dis[node];
    float2 xv = X2[node * C2 + lane];
    float2 acc = make_float2(xv.x * di, xv.y * di);   // self: dis_i * x_i

    int j = beg;
    for (; j + 4 <= end; j += 4) {
        int s0 = g_csr[j + 0], s1 = g_csr[j + 1];
        int s2 = g_csr[j + 2], s3 = g_csr[j + 3];
        float d0 = g_dis[s0], d1 = g_dis[s1], d2 = g_dis[s2], d3 = g_dis[s3];
        float2 v0 = X2[s0 * C2 + lane];
        float2 v1 = X2[s1 * C2 + lane];
        float2 v2 = X2[s2 * C2 + lane];
        float2 v3 = X2[s3 * C2 + lane];
        acc.x = fmaf(v0.x, d0, fmaf(v1.x, d1, fmaf(v2.x, d2, fmaf(v3.x, d3, acc.x))));
        acc.y = fmaf(v0.y, d0, fmaf(v1.y, d1, fmaf(v2.y, d2, fmaf(v3.y, d3, acc.y))));
    }
    for (; j < end; j++) {
        int s0 = g_csr[j];
        float d0 = g_dis[s0];
        float2 v = X2[s0 * C2 + lane];
        acc.x = fmaf(v.x, d0, acc.x);
        acc.y = fmaf(v.y, d0, acc.y);
    }
    ((float2*)Z)[node * C2 + lane] = make_float2(di * acc.x, di * acc.y);
}

// Layer-2 agg on PRE-SCALED hs2 (64f):
//   out_i = sigmoid( dis_i * ( hs2_i + sum_e hs2_src ) + b2 )
__device__ __forceinline__ void agg2_node(int node, const float2* __restrict__ H2,
                                          const float* __restrict__ b,
                                          float* __restrict__ OUT, int lane) {
    constexpr int C2 = D2 / 2;   // 32
    int beg = g_row[node], end = g_row[node + 1];
    float2 acc = H2[node * C2 + lane];
    int j = beg;
    for (; j + 4 <= end; j += 4) {
        int s0 = g_csr[j + 0], s1 = g_csr[j + 1];
        int s2 = g_csr[j + 2], s3 = g_csr[j + 3];
        float2 v0 = H2[s0 * C2 + lane];
        float2 v1 = H2[s1 * C2 + lane];
        float2 v2 = H2[s2 * C2 + lane];
        float2 v3 = H2[s3 * C2 + lane];
        acc.x += (v0.x + v1.x) + (v2.x + v3.x);
        acc.y += (v0.y + v1.y) + (v2.y + v3.y);
    }
    for (; j < end; j++) {
        int s0 = g_csr[j];
        float2 v = H2[s0 * C2 + lane];
        acc.x += v.x; acc.y += v.y;
    }
    float d = g_dis[node];
    float2 bb = ((const float2*)b)[lane];
    float2 o;
    o.x = act_sigmoid(fmaf(d, acc.x, bb.x));
    o.y = act_sigmoid(fmaf(d, acc.y, bb.y));
    ((float2*)OUT)[node * C2 + lane] = o;
}

// ---------------- the single fused persistent kernel -----------------------
// smem: sW1 24KB + sW2 24KB + sT 12KB + scan 1KB + b1 384B ~= 62.5KB
// -> 3 blocks/SM.
__global__ void __launch_bounds__(NT, 3)
k_fused(const float* __restrict__ x, const void* __restrict__ ep,
        const float* __restrict__ W1, const float* __restrict__ b1,
        const float* __restrict__ W2, const float* __restrict__ b2,
        float* __restrict__ out) {
    __shared__ __align__(16) float sW1[D0 * D1];   // 6144 floats
    __shared__ __align__(16) float sW2[D1 * D2];   // 6144 floats
    __shared__ __align__(16) float sT [32 * D1];   // z tile (32x64) then h tile (32x96)
    __shared__ float sB1[D1];
    __shared__ int   sScan[NT];
    __shared__ int   s_nz;
    __shared__ int   sSteal;

    int t   = threadIdx.x;
    int blk = blockIdx.x;
    int gid = blk * NT + t;
    int w   = t >> 5, lane = t & 31;

    // ---- P0: zero histogram; block 0 detects edge dtype; reset steal[2].
    // Values in [0,50000): little-endian int64 => odd 32-bit words of the
    // first 1024 entries are all 0; int32 => they are random edge ids.
    if (gid == 0) g_steal[2] = 0;
    for (int i = gid; i < NN; i += GRID * NT) g_cnt[i] = 0;
    if (blk == 0) {
        const int* e = (const int*)ep;
        int local = 0;
#pragma unroll
        for (int q = 0; q < 4; q++) local |= e[2 * (t * 4 + q) + 1];
        if (t == 0) s_nz = 0;
        __syncthreads();
        if (local) atomicOr(&s_nz, 1);
        __syncthreads();
        if (t == 0) g_is64 = (s_nz == 0) ? 1 : 0;
    }
    gbar();
    int is64 = __ldcg(&g_is64);

    // ---- P1: in-degree histogram
    if (is64) {
        const longlong2* p = (const longlong2*)ep;
        for (int i = gid; i < NE / 2; i += GRID * NT) {
            longlong2 dd = p[NE / 2 + i];
            atomicAdd(&g_cnt[(int)dd.x], 1);
            atomicAdd(&g_cnt[(int)dd.y], 1);
        }
    } else {
        const int2* p = (const int2*)ep;
        for (int i = gid; i < NE / 2; i += GRID * NT) {
            int2 dd = p[NE / 2 + i];
            atomicAdd(&g_cnt[dd.x], 1);
            atomicAdd(&g_cnt[dd.y], 1);
        }
    }
    gbar();

    // ---- P2a: block-strided inclusive scan of counts (NN/GRID per block...)
    // one node per thread, blocks cover [blk*NT, blk*NT+NT) then stride.
    // NN=50000 < GRID*NT=113664, single pass suffices.
    int c = (gid < NN) ? __ldcg(&g_cnt[gid]) : 0;
    sScan[t] = c;
    __syncthreads();
#pragma unroll
    for (int off = 1; off < NT; off <<= 1) {
        int v = sScan[t];
        int a = (t >= off) ? sScan[t - off] : 0;
        __syncthreads();
        sScan[t] = v + a;
        __syncthreads();
    }
    int incl = sScan[t];
    if (t == NT - 1) g_bsum[blk] = incl;
    gbar();

    // ---- P2b: block 0 scans the GRID block totals
    if (blk == 0) {
        constexpr int PB = (GRID + NT - 1) / NT;   // 2
        int loc[PB];
        int s = 0;
#pragma unroll
        for (int q = 0; q < PB; q++) {
            int idx = t * PB + q;
            loc[q] = (idx < GRID) ? __ldcg(&g_bsum[idx]) : 0;
            s += loc[q];
        }
        sScan[t] = s;
        __syncthreads();
#pragma unroll
        for (int off = 1; off < NT; off <<= 1) {
            int v = sScan[t];
            int ad = (t >= off) ? sScan[t - off] : 0;
            __syncthreads();
            sScan[t] = v + ad;
            __syncthreads();
        }
        int run = sScan[t] - s;
#pragma unroll
        for (int q = 0; q < PB; q++) {
            int idx = t * PB + q;
            if (idx < GRID) { g_bpre[idx] = run; run += loc[q]; }
        }
    }
    gbar();

    // ---- P2c: write row/cur/dis
    if (gid < NN) {
        int base = __ldcg(&g_bpre[blk]);
        int excl = base + incl - c;
        g_row[gid] = excl;
        g_cur[gid] = excl;
        g_dis[gid] = rsqrtf((float)c + 1.0f);
    }
    if (gid == 0) g_row[NN] = NE;
    gbar();

    // ---- P3: CSR scatter
    if (is64) {
        const long long* p = (const long long*)ep;
        for (int e = gid; e < NE; e += GRID * NT) {
            int s = (int)p[e];
            int d = (int)p[NE + e];
            int pos = atomicAdd(&g_cur[d], 1);
            g_csr[pos] = s;
        }
    } else {
        const int* p = (const int*)ep;
        for (int e = gid; e < NE; e += GRID * NT) {
            int s = p[e];
            int d = p[NE + e];
            int pos = atomicAdd(&g_cur[d], 1);
            g_csr[pos] = s;
        }
    }
    gbar();

    // ---- P4: aggregate RAW x -> z (stolen chunks of 16 nodes, 2/warp)
    {
        const float2* X2 = (const float2*)x;
        for (;;) {
            __syncthreads();
            if (t == 0) sSteal = (int)atomicAdd(&g_steal[0], 1u);
            __syncthreads();
            int base = sSteal * 16;
            if (base >= NN) break;
#pragma unroll
            for (int q = 0; q < 2; q++) {
                int node = base + w * 2 + q;
                if (node < NN) aggx_node(node, X2, g_z, lane);
            }
        }
    }
    gbar();

    // ---- P5: FUSED double GEMM per 32-row tile (stolen); reset steal[0].
    // h = relu(z@W1 + b1) lives ONLY in smem; hs2 = (h@W2)*dis -> gmem.
    if (gid == 0) g_steal[0] = 0;
    {
        // stage W1, W2, b1 once per block
        for (int i = t; i < D0 * D1 / 4; i += NT)
            ((float4*)sW1)[i] = ((const float4*)W1)[i];
        for (int i = t; i < D1 * D2 / 4; i += NT)
            ((float4*)sW2)[i] = ((const float4*)W2)[i];
        if (t < D1) sB1[t] = b1[t];

        int rbase = w * 4;
        const int ntile = (NN + 31) / 32;
        for (;;) {
            __syncthreads();   // W/b staged; prior iter done with sT+sSteal
            if (t == 0) sSteal = (int)atomicAdd(&g_steal[1], 1u);
            __syncthreads();
            int tile = *(volatile int*)&sSteal;
            if (tile >= ntile) break;
            int row0 = tile * 32;

            // stage z tile [32][64] (float4)
            for (int i = t; i < 32 * (D0 / 4); i += NT) {
                int r = i / (D0 / 4), k4 = i % (D0 / 4);
                int gr = row0 + r;
                ((float4*)sT)[i] = (gr < NN)
                    ? ((const float4*)g_z)[gr * (D0 / 4) + k4]
                    : make_float4(0.f, 0.f, 0.f, 0.f);
            }
            __syncthreads();

            // GEMM1: acc1[r][c] = sum_k z[r][k] * W1[k][96]
            float acc1[4][3];
#pragma unroll
            for (int r = 0; r < 4; r++)
#pragma unroll
                for (int cc = 0; cc < 3; cc++) acc1[r][cc] = 0.0f;
#pragma unroll
            for (int k = 0; k < D0; k++) {
                float wv[3];
#pragma unroll
                for (int cc = 0; cc < 3; cc++) wv[cc] = sW1[k * D1 + lane + 32 * cc];
                float xv[4];
#pragma unroll
                for (int r = 0; r < 4; r++) xv[r] = sT[(rbase + r) * D0 + k];
#pragma unroll
                for (int r = 0; r < 4; r++)
#pragma unroll
                    for (int cc = 0; cc < 3; cc++)
                        acc1[r][cc] = fmaf(xv[r], wv[cc], acc1[r][cc]);
            }
            __syncthreads();   // everyone done reading z from sT

            // h = relu(acc1 + b1) -> sT as [32][96]
#pragma unroll
            for (int r = 0; r < 4; r++)
#pragma unroll
                for (int cc = 0; cc < 3; cc++)
                    sT[(rbase + r) * D1 + lane + 32 * cc] =
                        act_relu(acc1[r][cc] + sB1[lane + 32 * cc]);
            __syncthreads();   // h tile complete

            // GEMM2: acc2[r][c] = sum_k h[r][k] * W2[k][64]; scale by dis
            float acc2[4][2];
#pragma unroll
            for (int r = 0; r < 4; r++)
#pragma unroll
                for (int cc = 0; cc < 2; cc++) acc2[r][cc] = 0.0f;
#pragma unroll
            for (int k = 0; k < D1; k++) {
                float wv[2];
#pragma unroll
                for (int cc = 0; cc < 2; cc++) wv[cc] = sW2[k * D2 + lane + 32 * cc];
                float hv[4];
#pragma unroll
                for (int r = 0; r < 4; r++) hv[r] = sT[(rbase + r) * D1 + k];
#pragma unroll
                for (int r = 0; r < 4; r++)
#pragma unroll
                    for (int cc = 0; cc < 2; cc++)
                        acc2[r][cc] = fmaf(hv[r], wv[cc], acc2[r][cc]);
            }
#pragma unroll
            for (int r = 0; r < 4; r++) {
                int gr = row0 + rbase + r;
                if (gr < NN) {
                    float d = g_dis[gr];
#pragma unroll
                    for (int cc = 0; cc < 2; cc++)
                        g_hs2[gr * D2 + lane + 32 * cc] = acc2[r][cc] * d;
                }
            }
        }
    }
    gbar();

    // ---- P6: layer-2 aggregation (stolen); reset steal[1]
    if (gid == 0) g_steal[1] = 0;
    {
        const float2* H2 = (const float2*)g_hs2;
        for (;;) {
            __syncthreads();
            if (t == 0) sSteal = (int)atomicAdd(&g_steal[2], 1u);
            __syncthreads();
            int base = sSteal * 16;
            if (base >= NN) break;
#pragma unroll
            for (int q = 0; q < 2; q++) {
                int node = base + w * 2 + q;
                if (node < NN) agg2_node(node, H2, b2, out, lane);
            }
        }
    }
}

// ---------------- launch: ONE kernel ---------------------------------------
extern "C" void kernel_launch(void* const* d_in, const int* in_sizes, int n_in,
                              void* d_out, int out_size) {
    const float* x  = (const float*)d_in[0];
    const void*  ei = d_in[1];
    const float* W1 = (const float*)d_in[2];
    const float* b1 = (const float*)d_in[3];
    const float* W2 = (const float*)d_in[4];
    const float* b2 = (const float*)d_in[5];
    float* out = (float*)d_out;

    k_fused<<<GRID, NT>>>(x, ei, W1, b1, W2, b2, out);
}